// round 13
// baseline (speedup 1.0000x reference)
#include <cuda_runtime.h>
#include <math.h>

// Problem dims
#define B_ 128
#define T_ 512
#define J_ 700
#define JP 704            // J padded to /8 and /4
#define H_ 512
#define O_ 20
#define M_ (B_ * T_)      // 65536 rows = (t*B + b)

// ---------------------------------------------------------------------------
// Scratch (device globals; no cudaMalloc allowed)
// ---------------------------------------------------------------------------
__device__ float g_xpad[M_ * JP];          // [M, JP] t-major padded input
__device__ float g_w1p[H_ * JP];           // W1 padded
__device__ float g_act1[M_ * H_];          // layer1 preact -> spikes (in place)
__device__ float g_act2[M_ * H_];          // layer2 preact -> spikes (in place)
__device__ float g_a3[M_ * O_];            // readout preact
__device__ float g_stats1[2 * H_];
__device__ float g_stats2[2 * H_];
__device__ float g_stats3[2 * O_];
__device__ float g_scale1[H_], g_shift1[H_], g_beta1[H_];
__device__ float g_scale2[H_], g_shift2[H_], g_beta2[H_];
__device__ float g_scaler[O_], g_shiftr[O_], g_betar[O_];

// ---------------------------------------------------------------------------
// Utility kernels
// ---------------------------------------------------------------------------
__global__ void zero_stats(float* s1, float* s2, float* s3) {
    int i = threadIdx.x;
    if (i < 2 * H_) { s1[i] = 0.0f; s2[i] = 0.0f; }
    if (i < 2 * O_) s3[i] = 0.0f;
}

__global__ void pad_w1(const float* __restrict__ W1, float* __restrict__ Wp) {
    int i = blockIdx.x * blockDim.x + threadIdx.x;
    if (i < H_ * JP) {
        int r = i / JP, c = i % JP;
        Wp[i] = (c < J_) ? W1[r * J_ + c] : 0.0f;
    }
}

// x [B,T,J] -> xpad [T*B, JP] with zero pad
__global__ void transpose_pad_x(const float* __restrict__ x, float* __restrict__ xp) {
    int m = blockIdx.x;            // m = t*B + b
    int t = m / B_;
    int b = m - t * B_;
    const float* src = x + ((size_t)b * T_ + t) * J_;
    float* dst = xp + (size_t)m * JP;
    for (int j = threadIdx.x; j < JP; j += blockDim.x)
        dst[j] = (j < J_) ? src[j] : 0.0f;
}

// ---------------------------------------------------------------------------
// SGEMM: C[m,n] = sum_k A[m,k] * W[n,k]   (A: [M,K], W: [N,K], C: [M,N])
// 128x128 tile, BK=8, 256 threads, 8x8 per thread. K % 8 == 0, M,N % 128 == 0.
// ---------------------------------------------------------------------------
__global__ void __launch_bounds__(256, 2)
sgemm_tn(const float* __restrict__ A, const float* __restrict__ W,
         float* __restrict__ C, int N, int K) {
    __shared__ __align__(16) float As[8][128];
    __shared__ __align__(16) float Bs[8][128];
    const int tid = threadIdx.x;
    const int tx = tid & 15;
    const int ty = tid >> 4;
    const int lr = tid >> 1;           // 0..127
    const int lc = (tid & 1) << 2;     // 0 or 4

    const float* Ag = A + (size_t)(blockIdx.y * 128 + lr) * K + lc;
    const float* Wg = W + (size_t)(blockIdx.x * 128 + lr) * K + lc;

    float acc[8][8];
#pragma unroll
    for (int i = 0; i < 8; i++)
#pragma unroll
        for (int j = 0; j < 8; j++) acc[i][j] = 0.0f;

    for (int k0 = 0; k0 < K; k0 += 8) {
        float4 a4 = *(const float4*)(Ag + k0);
        float4 b4 = *(const float4*)(Wg + k0);
        As[lc + 0][lr] = a4.x; As[lc + 1][lr] = a4.y;
        As[lc + 2][lr] = a4.z; As[lc + 3][lr] = a4.w;
        Bs[lc + 0][lr] = b4.x; Bs[lc + 1][lr] = b4.y;
        Bs[lc + 2][lr] = b4.z; Bs[lc + 3][lr] = b4.w;
        __syncthreads();
#pragma unroll
        for (int k = 0; k < 8; k++) {
            float4 a0 = *(const float4*)&As[k][ty * 8];
            float4 a1 = *(const float4*)&As[k][ty * 8 + 4];
            float4 b0 = *(const float4*)&Bs[k][tx * 8];
            float4 b1 = *(const float4*)&Bs[k][tx * 8 + 4];
            float a[8] = {a0.x, a0.y, a0.z, a0.w, a1.x, a1.y, a1.z, a1.w};
            float b[8] = {b0.x, b0.y, b0.z, b0.w, b1.x, b1.y, b1.z, b1.w};
#pragma unroll
            for (int i = 0; i < 8; i++)
#pragma unroll
                for (int j = 0; j < 8; j++)
                    acc[i][j] = fmaf(a[i], b[j], acc[i][j]);
        }
        __syncthreads();
    }

    float* Crow = C + (size_t)(blockIdx.y * 128 + ty * 8) * N + blockIdx.x * 128 + tx * 8;
#pragma unroll
    for (int i = 0; i < 8; i++) {
        *(float4*)(Crow + (size_t)i * N) =
            make_float4(acc[i][0], acc[i][1], acc[i][2], acc[i][3]);
        *(float4*)(Crow + (size_t)i * N + 4) =
            make_float4(acc[i][4], acc[i][5], acc[i][6], acc[i][7]);
    }
}

// ---------------------------------------------------------------------------
// Per-channel sum/sumsq over [M_, H_] matrix. grid=512 blocks, block=512 thr.
// ---------------------------------------------------------------------------
__global__ void colstats512(const float* __restrict__ X, float* __restrict__ stats) {
    int c = threadIdx.x;                       // channel
    int rows = M_ / gridDim.x;
    size_t r0 = (size_t)blockIdx.x * rows;
    float s = 0.0f, q = 0.0f;
    const float* p = X + r0 * H_ + c;
    for (int r = 0; r < rows; r++, p += H_) {
        float v = *p;
        s += v;
        q += v * v;
    }
    atomicAdd(&stats[c], s);
    atomicAdd(&stats[H_ + c], q);
}

// Per-channel stats over [M_, O_] (20 channels) via shared atomics
__global__ void colstats20(const float* __restrict__ X, float* __restrict__ stats) {
    __shared__ float ss[O_], qq[O_];
    if (threadIdx.x < O_) { ss[threadIdx.x] = 0.0f; qq[threadIdx.x] = 0.0f; }
    __syncthreads();
    const int total = M_ * O_;
    for (int e = blockIdx.x * blockDim.x + threadIdx.x; e < total;
         e += gridDim.x * blockDim.x) {
        float v = X[e];
        int c = e % O_;
        atomicAdd(&ss[c], v);
        atomicAdd(&qq[c], v * v);
    }
    __syncthreads();
    if (threadIdx.x < O_) {
        atomicAdd(&stats[threadIdx.x], ss[threadIdx.x]);
        atomicAdd(&stats[O_ + threadIdx.x], qq[threadIdx.x]);
    }
}

// scale = gamma * rsqrt(var+eps); shift = bias - mean*scale; beta = sigmoid(raw)
__global__ void bn_finalize(const float* __restrict__ stats,
                            const float* __restrict__ gamma,
                            const float* __restrict__ bias,
                            const float* __restrict__ beta_raw,
                            float* __restrict__ scale, float* __restrict__ shift,
                            float* __restrict__ beta, int C, float invM) {
    int c = blockIdx.x * blockDim.x + threadIdx.x;
    if (c >= C) return;
    float mean = stats[c] * invM;
    float var = stats[C + c] * invM - mean * mean;
    float sc = gamma[c] * rsqrtf(var + 1e-5f);
    scale[c] = sc;
    shift[c] = bias[c] - mean * sc;
    beta[c] = 1.0f / (1.0f + expf(-beta_raw[c]));
}

// ---------------------------------------------------------------------------
// LIF scan (non-readout). One thread per (b,i) chain; in-place spike write.
// X layout: [T, B*H], stride B*H = 65536 per timestep.
// ---------------------------------------------------------------------------
__global__ void lif_scan(float* __restrict__ X, const float* __restrict__ scale,
                         const float* __restrict__ shift,
                         const float* __restrict__ beta) {
    int idx = blockIdx.x * blockDim.x + threadIdx.x;   // 0..65535
    int c = idx & (H_ - 1);
    float sc = scale[c], sh = shift[c], be = beta[c];
    float omb = 1.0f - be;
    float U = 0.0f, S = 0.0f;
    size_t off = idx;
    float xn = X[off];
#pragma unroll 4
    for (int t = 0; t < T_; t++) {
        float xh = xn * sc + sh;
        if (t + 1 < T_) xn = X[off + (size_t)(B_ * H_)];   // prefetch next t
        U = be * (U - S) + omb * xh;
        S = (U > 1.0f) ? 1.0f : 0.0f;
        X[off] = S;
        off += (size_t)(B_ * H_);
    }
}

// ---------------------------------------------------------------------------
// Readout GEMM: A3[m,o] = sum_k S[m,k] * Wr[o,k]. Warp per row, Wr in smem.
// ---------------------------------------------------------------------------
__global__ void __launch_bounds__(256)
readout_gemm(const float* __restrict__ S, const float* __restrict__ Wr,
             float* __restrict__ A3) {
    __shared__ __align__(16) float w[O_ * H_];   // 40 KB
    for (int i = threadIdx.x; i < O_ * H_; i += blockDim.x) w[i] = Wr[i];
    __syncthreads();
    int lane = threadIdx.x & 31;
    int warp = threadIdx.x >> 5;
    int wpb = blockDim.x >> 5;
    int nwarps = wpb * gridDim.x;
    for (int m = blockIdx.x * wpb + warp; m < M_; m += nwarps) {
        const float4* row = (const float4*)(S + (size_t)m * H_);
        float acc[O_];
#pragma unroll
        for (int o = 0; o < O_; o++) acc[o] = 0.0f;
#pragma unroll
        for (int it = 0; it < 4; it++) {
            int q = lane + 32 * it;              // float4 index into 512-row
            float4 v = row[q];
#pragma unroll
            for (int o = 0; o < O_; o++) {
                float4 wv = *(const float4*)&w[o * H_ + q * 4];
                acc[o] += v.x * wv.x + v.y * wv.y + v.z * wv.z + v.w * wv.w;
            }
        }
#pragma unroll
        for (int o = 0; o < O_; o++)
#pragma unroll
            for (int d = 16; d; d >>= 1)
                acc[o] += __shfl_xor_sync(0xffffffffu, acc[o], d);
        if (lane < O_) A3[(size_t)m * O_ + lane] = acc[lane];
    }
}

// ---------------------------------------------------------------------------
// Readout: leaky integrate (no spike) + softmax over O + sum over T.
// One warp per batch element; lane o < 20 owns channel o.
// ---------------------------------------------------------------------------
__global__ void readout_scan(const float* __restrict__ A3,
                             const float* __restrict__ scale,
                             const float* __restrict__ shift,
                             const float* __restrict__ beta,
                             float* __restrict__ out) {
    int b = blockIdx.x;
    int o = threadIdx.x;           // 32 lanes
    bool act = o < O_;
    float sc = act ? scale[o] : 0.0f;
    float sh = act ? shift[o] : 0.0f;
    float be = act ? beta[o] : 0.0f;
    float omb = 1.0f - be;
    float U = 0.0f, accum = 0.0f;
    for (int t = 0; t < T_; t++) {
        float xv = act ? A3[((size_t)t * B_ + b) * O_ + o] : 0.0f;
        U = be * U + omb * (xv * sc + sh);
        float uval = act ? U : -3.402823466e38f;
        float mx = uval;
#pragma unroll
        for (int d = 16; d; d >>= 1)
            mx = fmaxf(mx, __shfl_xor_sync(0xffffffffu, mx, d));
        float e = act ? expf(U - mx) : 0.0f;
        float s = e;
#pragma unroll
        for (int d = 16; d; d >>= 1)
            s += __shfl_xor_sync(0xffffffffu, s, d);
        accum += e / s;
    }
    if (act) out[b * O_ + o] = accum;
}

// ---------------------------------------------------------------------------
// Launch
// ---------------------------------------------------------------------------
extern "C" void kernel_launch(void* const* d_in, const int* in_sizes, int n_in,
                              void* d_out, int out_size) {
    const float* x   = (const float*)d_in[0];
    const float* W1  = (const float*)d_in[1];
    const float* be1 = (const float*)d_in[2];
    const float* g1  = (const float*)d_in[3];
    const float* b1  = (const float*)d_in[4];
    const float* W2  = (const float*)d_in[5];
    const float* be2 = (const float*)d_in[6];
    const float* g2  = (const float*)d_in[7];
    const float* b2  = (const float*)d_in[8];
    const float* Wr  = (const float*)d_in[9];
    const float* ber = (const float*)d_in[10];
    const float* gr  = (const float*)d_in[11];
    const float* br  = (const float*)d_in[12];
    float* out = (float*)d_out;

    float *xpad, *w1p, *act1, *act2, *a3, *st1, *st2, *st3;
    float *sc1, *sh1, *bt1, *sc2, *sh2, *bt2, *scr, *shr, *btr;
    cudaGetSymbolAddress((void**)&xpad, g_xpad);
    cudaGetSymbolAddress((void**)&w1p,  g_w1p);
    cudaGetSymbolAddress((void**)&act1, g_act1);
    cudaGetSymbolAddress((void**)&act2, g_act2);
    cudaGetSymbolAddress((void**)&a3,   g_a3);
    cudaGetSymbolAddress((void**)&st1,  g_stats1);
    cudaGetSymbolAddress((void**)&st2,  g_stats2);
    cudaGetSymbolAddress((void**)&st3,  g_stats3);
    cudaGetSymbolAddress((void**)&sc1,  g_scale1);
    cudaGetSymbolAddress((void**)&sh1,  g_shift1);
    cudaGetSymbolAddress((void**)&bt1,  g_beta1);
    cudaGetSymbolAddress((void**)&sc2,  g_scale2);
    cudaGetSymbolAddress((void**)&sh2,  g_shift2);
    cudaGetSymbolAddress((void**)&bt2,  g_beta2);
    cudaGetSymbolAddress((void**)&scr,  g_scaler);
    cudaGetSymbolAddress((void**)&shr,  g_shiftr);
    cudaGetSymbolAddress((void**)&btr,  g_betar);

    const float invM = 1.0f / (float)M_;

    zero_stats<<<1, 1024>>>(st1, st2, st3);
    pad_w1<<<(H_ * JP + 255) / 256, 256>>>(W1, w1p);
    transpose_pad_x<<<M_, 256>>>(x, xpad);

    // Layer 1
    sgemm_tn<<<dim3(H_ / 128, M_ / 128), 256>>>(xpad, w1p, act1, H_, JP);
    colstats512<<<512, 512>>>(act1, st1);
    bn_finalize<<<1, 512>>>(st1, g1, b1, be1, sc1, sh1, bt1, H_, invM);
    lif_scan<<<256, 256>>>(act1, sc1, sh1, bt1);

    // Layer 2
    sgemm_tn<<<dim3(H_ / 128, M_ / 128), 256>>>(act1, W2, act2, H_, H_);
    colstats512<<<512, 512>>>(act2, st2);
    bn_finalize<<<1, 512>>>(st2, g2, b2, be2, sc2, sh2, bt2, H_, invM);
    lif_scan<<<256, 256>>>(act2, sc2, sh2, bt2);

    // Readout
    readout_gemm<<<2048, 256>>>(act2, Wr, a3);
    colstats20<<<256, 256>>>(a3, st3);
    bn_finalize<<<1, 32>>>(st3, gr, br, ber, scr, shr, btr, O_, invM);
    readout_scan<<<B_, 32>>>(a3, scr, shr, btr, out);
}